// round 14
// baseline (speedup 1.0000x reference)
#include <cuda_runtime.h>
#include <cuda.h>
#include <cstdint>

// PointPillarScatter on GB300 (sm_103a).
// out[b, c, y, x] = feat[p, c] where idxmap cell == p+1, else 0.
//
// Round 13 -> 14: REVERT to the R12 optimum (TMA depth 2, 8-channel chunks;
// depth 4 regressed: extra barriers, no DRAM% gain -> memory system is the
// plateau at ~5.4 TB/s). Micro-cleanup: per-thread s_list entries hoisted
// into registers before the chunk loop (removes per-chunk LDS re-reads).
// PDL overlap of scatter with the zero prologue retained.

#define NX_ 432
#define NY_ 496
#define C_  64
#define B_  8
#define NCELLS (B_ * NY_ * NX_)      // 1,714,176
#define CHUNK_C 8                    // channels per TMA store
#define NCHUNKS (C_ / CHUNK_C)       // 8

__device__ __align__(16) int g_idxmap[NCELLS];   // zero-init = all empty

// ---------------------------------------------------------------------------
// Kernel 1: scatter pillar index (p+1), with per-block dtype detection.
// ---------------------------------------------------------------------------
__global__ void scatter_idx_kernel(const void* __restrict__ coords, int P) {
    __shared__ int s_is64;
    if (threadIdx.x < 32) {
        const long long* c64 = (const long long*)coords;
        int rows = P < 64 ? P : 64;
        int ok = 1;
        for (int p = threadIdx.x; p < rows; p += 32) {
            for (int j = 0; j < 4; j++) {
                long long v = c64[4 * p + j];
                if (v < 0 || v >= (1LL << 20)) ok = 0;
            }
        }
        ok = __all_sync(0xFFFFFFFFu, ok);
        if (threadIdx.x == 0) s_is64 = ok;
    }
    __syncthreads();

    int p = blockIdx.x * blockDim.x + threadIdx.x;
    if (p < P) {
        int b, z, y, x;
        if (s_is64) {
            const long long* c = (const long long*)coords;
            b = (int)c[4 * p + 0]; z = (int)c[4 * p + 1];
            y = (int)c[4 * p + 2]; x = (int)c[4 * p + 3];
        } else {
            const int* c = (const int*)coords;
            b = c[4 * p + 0]; z = c[4 * p + 1];
            y = c[4 * p + 2]; x = c[4 * p + 3];
        }
        if (b >= 0 && b < B_) {
            int lin = z + y * NX_ + x;
            if (lin >= 0 && lin < NY_ * NX_)
                g_idxmap[b * (NY_ * NX_) + lin] = p + 1;  // 0 stays "empty"
        }
    }
    cudaTriggerProgrammaticLaunchCompletion();
}

// ---------------------------------------------------------------------------
__device__ __forceinline__ uint32_t smem_u32(const void* p) {
    uint32_t a;
    asm("{ .reg .u64 t; cvta.to.shared.u64 t, %1; cvt.u32.u64 %0, t; }"
        : "=r"(a) : "l"(p));
    return a;
}

// ---------------------------------------------------------------------------
// Kernel 2 (TMA path): block = one (b, y) row of 432 cells.
// Two 13.8 KB buffers, 8-channel chunks, <=1 store pending overlap.
// ---------------------------------------------------------------------------
__global__ __launch_bounds__(256) void gather_tma_kernel(
    const float* __restrict__ feat,
    const __grid_constant__ CUtensorMap tmap)
{
    __shared__ __align__(128) float s_buf[2][CHUNK_C][NX_];  // 2 x 13,824 B
    __shared__ int s_list[NX_];      // (p << 9) | cell
    __shared__ int s_n;

    int tid = threadIdx.x;
    int y = blockIdx.x % NY_;
    int b = blockIdx.x / NY_;

    if (tid == 0) s_n = 0;
    // Zero both buffers ONCE (scatter-independent; overlaps scatter via PDL).
    float4* z = (float4*)&s_buf[0][0][0];
    #pragma unroll 4
    for (int i = tid; i < 2 * CHUNK_C * NX_ / 4; i += 256)
        z[i] = make_float4(0.0f, 0.0f, 0.0f, 0.0f);

    // Wait for the scatter grid's writes to be visible.
    cudaGridDependencySynchronize();
    __syncthreads();

    // Phase 1: idxmap read + self-clean + compact occupied cells.
    int cellbase = b * (NY_ * NX_) + y * NX_;
    for (int cell = tid; cell < NX_; cell += 256) {
        int m = g_idxmap[cellbase + cell];
        if (m != 0) {
            g_idxmap[cellbase + cell] = 0;       // restore for next replay
            int pos = atomicAdd(&s_n, 1);
            s_list[pos] = ((m - 1) << 9) | cell; // p, cell packed
        }
    }
    __syncthreads();
    int n_occ = s_n;
    const float4* feat4 = (const float4*)feat;

    // Hoist this thread's fill items into registers (<=4 with n_occ<=432):
    // item j covers (slot = j>>1, v = j&1).
    int   r_cell[4];
    const float4* r_src[4];
    int nitems = 0;
    for (int j = tid; j < n_occ * 2; j += 256) {
        int e = s_list[j >> 1];
        r_cell[nitems] = e & 511;
        r_src[nitems]  = feat4 + (size_t)(e >> 9) * 16 + (j & 1);
        nitems++;
    }

    for (int chunk = 0; chunk < NCHUNKS; chunk++) {
        float (*buf)[NX_] = s_buf[chunk & 1];
        // Fill occupied cells: 2 float4 (32B) per pillar for this chunk.
        #pragma unroll
        for (int k = 0; k < 4; k++) {
            if (k < nitems) {
                float4 f = r_src[k][chunk * 2];
                int v4   = ((k * 256 + tid) & 1) * 4;   // v from item parity
                int cell = r_cell[k];
                buf[v4 + 0][cell] = f.x;
                buf[v4 + 1][cell] = f.y;
                buf[v4 + 2][cell] = f.z;
                buf[v4 + 3][cell] = f.w;
            }
        }
        __syncthreads();
        if (tid == 0) {
            asm volatile("fence.proxy.async.shared::cta;" ::: "memory");
            uint32_t saddr = smem_u32(&buf[0][0]);
            int c0 = chunk * CHUNK_C;
            asm volatile(
                "cp.async.bulk.tensor.5d.global.shared::cta.tile.bulk_group "
                "[%0, {%1, %2, %3, %4, %5}], [%6];"
                :: "l"(&tmap), "r"(0), "r"(0), "r"(c0), "r"(y), "r"(b),
                   "r"(saddr)
                : "memory");
            asm volatile("cp.async.bulk.commit_group;" ::: "memory");
            // <=1 group pending -> chunk-1 done -> other buffer free.
            asm volatile("cp.async.bulk.wait_group 1;" ::: "memory");
        }
        __syncthreads();
    }
    if (tid == 0) asm volatile("cp.async.bulk.wait_group 0;" ::: "memory");
}

// ---------------------------------------------------------------------------
// Fallback gather (proven R10 path), used only if driver entry lookup fails.
// ---------------------------------------------------------------------------
#define TILE   108
#define TILES_X (NX_ / TILE)
#define QUADS  (TILE / 4)
#define CGROUPS 10
#define SLOTS  (QUADS * CGROUPS)
#define PITCH  116
#define CH_    32

__global__ __launch_bounds__(256) void gather_fallback_kernel(
    const float* __restrict__ feat, float* __restrict__ out)
{
    __shared__ float s_tile[CH_][PITCH];
    __shared__ __align__(16) int s_idx[PITCH];
    __shared__ int s_list[TILE];
    __shared__ int s_n;

    int bx = blockIdx.x;
    int tx = bx % TILES_X;
    int y  = (bx / TILES_X) % NY_;
    int b  = bx / (TILES_X * NY_);
    int x0 = tx * TILE;
    int tid = threadIdx.x;

    if (tid == 0) s_n = 0;
    if (tid >= TILE && tid < PITCH) s_idx[tid] = -1;
    __syncthreads();

    int cellbase = b * (NY_ * NX_) + y * NX_ + x0;
    if (tid < TILE) {
        int m = g_idxmap[cellbase + tid];
        if (m != 0) g_idxmap[cellbase + tid] = 0;
        s_idx[tid] = m - 1;
        if (m > 0) { int pos = atomicAdd(&s_n, 1); s_list[pos] = tid; }
    }
    __syncthreads();

    int n_occ = s_n;
    const float4* feat4 = (const float4*)feat;
    size_t outbase = (size_t)b * (C_ * NY_ * NX_) + (size_t)y * NX_ + x0;
    const int4* s_idx4 = (const int4*)s_idx;

    #pragma unroll
    for (int half = 0; half < 2; half++) {
        for (int j = tid; j < n_occ * 8; j += 256) {
            int slot = j >> 3, v = j & 7;
            int cell = s_list[slot];
            int p    = s_idx[cell];
            float4 f = feat4[(size_t)p * 16 + half * 8 + v];
            s_tile[4 * v + 0][cell] = f.x;
            s_tile[4 * v + 1][cell] = f.y;
            s_tile[4 * v + 2][cell] = f.z;
            s_tile[4 * v + 3][cell] = f.w;
        }
        __syncthreads();
        const float* outh = out + outbase + (size_t)(half * CH_) * (NY_ * NX_);
        for (int slot = tid; slot < SLOTS; slot += 256) {
            int q = slot % QUADS, c0 = slot / QUADS;
            int4 m = s_idx4[q];
            bool any = (m.x >= 0) | (m.y >= 0) | (m.z >= 0) | (m.w >= 0);
            const float* outq = outh + 4 * q;
            #pragma unroll
            for (int c = 0; c < CH_; c += CGROUPS) {
                int cc = c + c0;
                if (cc >= CH_) break;
                float4 v = make_float4(0.0f, 0.0f, 0.0f, 0.0f);
                if (any) {
                    float4 t = ((const float4*)s_tile[cc])[q];
                    if (m.x >= 0) v.x = t.x;
                    if (m.y >= 0) v.y = t.y;
                    if (m.z >= 0) v.z = t.z;
                    if (m.w >= 0) v.w = t.w;
                }
                __stcs((float4*)(outq + (size_t)cc * (NY_ * NX_)), v);
            }
        }
        if (half == 0) __syncthreads();
    }
}

// ---------------------------------------------------------------------------
typedef CUresult (*EncodeFn)(CUtensorMap*, CUtensorMapDataType, cuuint32_t,
    void*, const cuuint64_t*, const cuuint64_t*, const cuuint32_t*,
    const cuuint32_t*, CUtensorMapInterleave, CUtensorMapSwizzle,
    CUtensorMapL2promotion, CUtensorMapFloatOOBfill);

extern "C" void kernel_launch(void* const* d_in, const int* in_sizes, int n_in,
                              void* d_out, int out_size) {
    const float* feat   = (const float*)d_in[0];
    const void*  coords = d_in[1];
    int P = in_sizes[0] / C_;   // features are [P, 64] f32

    constexpr int TPB = 256;
    scatter_idx_kernel<<<(P + TPB - 1) / TPB, TPB>>>(coords, P);

    // Build the 5D output tensor map: [x_in=216, x_out=2, c, y, b].
    EncodeFn enc = nullptr;
    cudaDriverEntryPointQueryResult qr = cudaDriverEntryPointSymbolNotFound;
    cudaGetDriverEntryPointByVersion("cuTensorMapEncodeTiled", (void**)&enc,
                                     12000, cudaEnableDefault, &qr);
    bool tma_ok = (enc != nullptr) && (qr == cudaDriverEntryPointSuccess);

    CUtensorMap tmap;
    if (tma_ok) {
        cuuint64_t dims[5]    = {216, 2, C_, NY_, B_};
        cuuint64_t strides[4] = {216ull * 4,                       // x_out
                                 (cuuint64_t)NY_ * NX_ * 4,        // c
                                 (cuuint64_t)NX_ * 4,              // y
                                 (cuuint64_t)C_ * NY_ * NX_ * 4};  // b
        cuuint32_t box[5]  = {216, 2, CHUNK_C, 1, 1};
        cuuint32_t estr[5] = {1, 1, 1, 1, 1};
        CUresult r = enc(&tmap, CU_TENSOR_MAP_DATA_TYPE_FLOAT32, 5, d_out,
                         dims, strides, box, estr,
                         CU_TENSOR_MAP_INTERLEAVE_NONE,
                         CU_TENSOR_MAP_SWIZZLE_NONE,
                         CU_TENSOR_MAP_L2_PROMOTION_L2_128B,
                         CU_TENSOR_MAP_FLOAT_OOB_FILL_NONE);
        if (r != CUDA_SUCCESS) tma_ok = false;
    }

    if (tma_ok) {
        cudaLaunchAttribute attr[1];
        attr[0].id = cudaLaunchAttributeProgrammaticStreamSerialization;
        attr[0].val.programmaticStreamSerializationAllowed = 1;
        cudaLaunchConfig_t cfg = {};
        cfg.gridDim  = dim3(B_ * NY_, 1, 1);
        cfg.blockDim = dim3(TPB, 1, 1);
        cfg.attrs    = attr;
        cfg.numAttrs = 1;
        cudaLaunchKernelEx(&cfg, gather_tma_kernel, feat, tmap);
    } else {
        gather_fallback_kernel<<<B_ * NY_ * TILES_X, TPB>>>(feat, (float*)d_out);
    }
}

// round 15
// speedup vs baseline: 1.0933x; 1.0933x over previous
#include <cuda_runtime.h>
#include <cuda.h>
#include <cstdint>

// PointPillarScatter on GB300 (sm_103a).
// out[b, c, y, x] = feat[p, c] where idxmap cell == p+1, else 0.
//
// FINAL (= R12 optimum, 84.4 us): scatter(PDL) -> TMA-store gather.
//  - idxmap encodes p+1 (0 = empty), zero-init device global, self-cleaned
//    by the gather for graph-replay determinism.
//  - Gather block = one (b, y) row; two 13.8 KB smem buffers zeroed once
//    (occupied set identical across chunks -> fills overwrite stale data);
//    8 channel-chunks double-buffered via cp.async.bulk commit/wait.
//  - PDL overlaps the scatter with the gather's zeroing prologue.
// R13 (depth 4) and R14 (register-hoist -> local-mem spills) both regressed;
// this configuration is the measured optimum at the ~5.4 TB/s DRAM plateau.

#define NX_ 432
#define NY_ 496
#define C_  64
#define B_  8
#define NCELLS (B_ * NY_ * NX_)      // 1,714,176
#define CHUNK_C 8                    // channels per TMA store
#define NCHUNKS (C_ / CHUNK_C)       // 8

__device__ __align__(16) int g_idxmap[NCELLS];   // zero-init = all empty

// ---------------------------------------------------------------------------
// Kernel 1: scatter pillar index (p+1), with per-block dtype detection.
// ---------------------------------------------------------------------------
__global__ void scatter_idx_kernel(const void* __restrict__ coords, int P) {
    __shared__ int s_is64;
    if (threadIdx.x < 32) {
        const long long* c64 = (const long long*)coords;
        int rows = P < 64 ? P : 64;
        int ok = 1;
        for (int p = threadIdx.x; p < rows; p += 32) {
            for (int j = 0; j < 4; j++) {
                long long v = c64[4 * p + j];
                if (v < 0 || v >= (1LL << 20)) ok = 0;
            }
        }
        ok = __all_sync(0xFFFFFFFFu, ok);
        if (threadIdx.x == 0) s_is64 = ok;
    }
    __syncthreads();

    int p = blockIdx.x * blockDim.x + threadIdx.x;
    if (p < P) {
        int b, z, y, x;
        if (s_is64) {
            const long long* c = (const long long*)coords;
            b = (int)c[4 * p + 0]; z = (int)c[4 * p + 1];
            y = (int)c[4 * p + 2]; x = (int)c[4 * p + 3];
        } else {
            const int* c = (const int*)coords;
            b = c[4 * p + 0]; z = c[4 * p + 1];
            y = c[4 * p + 2]; x = c[4 * p + 3];
        }
        if (b >= 0 && b < B_) {
            int lin = z + y * NX_ + x;
            if (lin >= 0 && lin < NY_ * NX_)
                g_idxmap[b * (NY_ * NX_) + lin] = p + 1;  // 0 stays "empty"
        }
    }
    // Let the dependent gather grid begin launching (it still gridsyncs on
    // our full completion before reading idxmap).
    cudaTriggerProgrammaticLaunchCompletion();
}

// ---------------------------------------------------------------------------
__device__ __forceinline__ uint32_t smem_u32(const void* p) {
    uint32_t a;
    asm("{ .reg .u64 t; cvta.to.shared.u64 t, %1; cvt.u32.u64 %0, t; }"
        : "=r"(a) : "l"(p));
    return a;
}

// ---------------------------------------------------------------------------
// Kernel 2 (TMA path): block = one (b, y) row of 432 cells.
// ---------------------------------------------------------------------------
__global__ __launch_bounds__(256) void gather_tma_kernel(
    const float* __restrict__ feat,
    const __grid_constant__ CUtensorMap tmap)
{
    __shared__ __align__(128) float s_buf[2][CHUNK_C][NX_];  // 2 x 13,824 B
    __shared__ int s_list[NX_];      // (p << 9) | cell
    __shared__ int s_n;

    int tid = threadIdx.x;
    int y = blockIdx.x % NY_;
    int b = blockIdx.x / NY_;

    if (tid == 0) s_n = 0;
    // Zero both buffers ONCE (scatter-independent; overlaps with scatter
    // under PDL). Zeros persist; chunk fills overwrite the same cells.
    float4* z = (float4*)&s_buf[0][0][0];
    #pragma unroll 4
    for (int i = tid; i < 2 * CHUNK_C * NX_ / 4; i += 256)
        z[i] = make_float4(0.0f, 0.0f, 0.0f, 0.0f);

    // Wait for the scatter grid's writes to be visible.
    cudaGridDependencySynchronize();
    __syncthreads();

    // Phase 1: idxmap read + self-clean + compact occupied cells.
    int cellbase = b * (NY_ * NX_) + y * NX_;
    for (int cell = tid; cell < NX_; cell += 256) {
        int m = g_idxmap[cellbase + cell];
        if (m != 0) {
            g_idxmap[cellbase + cell] = 0;       // restore for next replay
            int pos = atomicAdd(&s_n, 1);
            s_list[pos] = ((m - 1) << 9) | cell; // p, cell packed
        }
    }
    __syncthreads();
    int n_occ = s_n;
    const float4* feat4 = (const float4*)feat;

    for (int chunk = 0; chunk < NCHUNKS; chunk++) {
        float (*buf)[NX_] = s_buf[chunk & 1];
        // Fill occupied cells: 2 float4 (32B) per pillar for this chunk.
        for (int j = tid; j < n_occ * 2; j += 256) {
            int slot = j >> 1;
            int v    = j & 1;
            int e    = s_list[slot];
            int cell = e & 511;
            int p    = e >> 9;
            float4 f = feat4[(size_t)p * 16 + chunk * 2 + v];
            buf[4 * v + 0][cell] = f.x;
            buf[4 * v + 1][cell] = f.y;
            buf[4 * v + 2][cell] = f.z;
            buf[4 * v + 3][cell] = f.w;
        }
        __syncthreads();
        if (tid == 0) {
            asm volatile("fence.proxy.async.shared::cta;" ::: "memory");
            uint32_t saddr = smem_u32(&buf[0][0]);
            int c0 = chunk * CHUNK_C;
            asm volatile(
                "cp.async.bulk.tensor.5d.global.shared::cta.tile.bulk_group "
                "[%0, {%1, %2, %3, %4, %5}], [%6];"
                :: "l"(&tmap), "r"(0), "r"(0), "r"(c0), "r"(y), "r"(b),
                   "r"(saddr)
                : "memory");
            asm volatile("cp.async.bulk.commit_group;" ::: "memory");
            // <=1 group pending -> chunk-1 done -> other buffer free.
            asm volatile("cp.async.bulk.wait_group 1;" ::: "memory");
        }
        __syncthreads();
    }
    if (tid == 0) asm volatile("cp.async.bulk.wait_group 0;" ::: "memory");
}

// ---------------------------------------------------------------------------
// Fallback gather (proven R10 path), used only if driver entry lookup fails.
// ---------------------------------------------------------------------------
#define TILE   108
#define TILES_X (NX_ / TILE)
#define QUADS  (TILE / 4)
#define CGROUPS 10
#define SLOTS  (QUADS * CGROUPS)
#define PITCH  116
#define CH_    32

__global__ __launch_bounds__(256) void gather_fallback_kernel(
    const float* __restrict__ feat, float* __restrict__ out)
{
    __shared__ float s_tile[CH_][PITCH];
    __shared__ __align__(16) int s_idx[PITCH];
    __shared__ int s_list[TILE];
    __shared__ int s_n;

    int bx = blockIdx.x;
    int tx = bx % TILES_X;
    int y  = (bx / TILES_X) % NY_;
    int b  = bx / (TILES_X * NY_);
    int x0 = tx * TILE;
    int tid = threadIdx.x;

    if (tid == 0) s_n = 0;
    if (tid >= TILE && tid < PITCH) s_idx[tid] = -1;
    __syncthreads();

    int cellbase = b * (NY_ * NX_) + y * NX_ + x0;
    if (tid < TILE) {
        int m = g_idxmap[cellbase + tid];
        if (m != 0) g_idxmap[cellbase + tid] = 0;
        s_idx[tid] = m - 1;
        if (m > 0) { int pos = atomicAdd(&s_n, 1); s_list[pos] = tid; }
    }
    __syncthreads();

    int n_occ = s_n;
    const float4* feat4 = (const float4*)feat;
    size_t outbase = (size_t)b * (C_ * NY_ * NX_) + (size_t)y * NX_ + x0;
    const int4* s_idx4 = (const int4*)s_idx;

    #pragma unroll
    for (int half = 0; half < 2; half++) {
        for (int j = tid; j < n_occ * 8; j += 256) {
            int slot = j >> 3, v = j & 7;
            int cell = s_list[slot];
            int p    = s_idx[cell];
            float4 f = feat4[(size_t)p * 16 + half * 8 + v];
            s_tile[4 * v + 0][cell] = f.x;
            s_tile[4 * v + 1][cell] = f.y;
            s_tile[4 * v + 2][cell] = f.z;
            s_tile[4 * v + 3][cell] = f.w;
        }
        __syncthreads();
        const float* outh = out + outbase + (size_t)(half * CH_) * (NY_ * NX_);
        for (int slot = tid; slot < SLOTS; slot += 256) {
            int q = slot % QUADS, c0 = slot / QUADS;
            int4 m = s_idx4[q];
            bool any = (m.x >= 0) | (m.y >= 0) | (m.z >= 0) | (m.w >= 0);
            const float* outq = outh + 4 * q;
            #pragma unroll
            for (int c = 0; c < CH_; c += CGROUPS) {
                int cc = c + c0;
                if (cc >= CH_) break;
                float4 v = make_float4(0.0f, 0.0f, 0.0f, 0.0f);
                if (any) {
                    float4 t = ((const float4*)s_tile[cc])[q];
                    if (m.x >= 0) v.x = t.x;
                    if (m.y >= 0) v.y = t.y;
                    if (m.z >= 0) v.z = t.z;
                    if (m.w >= 0) v.w = t.w;
                }
                __stcs((float4*)(outq + (size_t)cc * (NY_ * NX_)), v);
            }
        }
        if (half == 0) __syncthreads();
    }
}

// ---------------------------------------------------------------------------
typedef CUresult (*EncodeFn)(CUtensorMap*, CUtensorMapDataType, cuuint32_t,
    void*, const cuuint64_t*, const cuuint64_t*, const cuuint32_t*,
    const cuuint32_t*, CUtensorMapInterleave, CUtensorMapSwizzle,
    CUtensorMapL2promotion, CUtensorMapFloatOOBfill);

extern "C" void kernel_launch(void* const* d_in, const int* in_sizes, int n_in,
                              void* d_out, int out_size) {
    const float* feat   = (const float*)d_in[0];
    const void*  coords = d_in[1];
    int P = in_sizes[0] / C_;   // features are [P, 64] f32

    constexpr int TPB = 256;
    scatter_idx_kernel<<<(P + TPB - 1) / TPB, TPB>>>(coords, P);

    // Build the 5D output tensor map: [x_in=216, x_out=2, c, y, b].
    EncodeFn enc = nullptr;
    cudaDriverEntryPointQueryResult qr = cudaDriverEntryPointSymbolNotFound;
    cudaGetDriverEntryPointByVersion("cuTensorMapEncodeTiled", (void**)&enc,
                                     12000, cudaEnableDefault, &qr);
    bool tma_ok = (enc != nullptr) && (qr == cudaDriverEntryPointSuccess);

    CUtensorMap tmap;
    if (tma_ok) {
        cuuint64_t dims[5]    = {216, 2, C_, NY_, B_};
        cuuint64_t strides[4] = {216ull * 4,                       // x_out
                                 (cuuint64_t)NY_ * NX_ * 4,        // c
                                 (cuuint64_t)NX_ * 4,              // y
                                 (cuuint64_t)C_ * NY_ * NX_ * 4};  // b
        cuuint32_t box[5]  = {216, 2, CHUNK_C, 1, 1};
        cuuint32_t estr[5] = {1, 1, 1, 1, 1};
        CUresult r = enc(&tmap, CU_TENSOR_MAP_DATA_TYPE_FLOAT32, 5, d_out,
                         dims, strides, box, estr,
                         CU_TENSOR_MAP_INTERLEAVE_NONE,
                         CU_TENSOR_MAP_SWIZZLE_NONE,
                         CU_TENSOR_MAP_L2_PROMOTION_L2_128B,
                         CU_TENSOR_MAP_FLOAT_OOB_FILL_NONE);
        if (r != CUDA_SUCCESS) tma_ok = false;
    }

    if (tma_ok) {
        // PDL launch: overlap gather's zeroing prologue with the scatter.
        cudaLaunchAttribute attr[1];
        attr[0].id = cudaLaunchAttributeProgrammaticStreamSerialization;
        attr[0].val.programmaticStreamSerializationAllowed = 1;
        cudaLaunchConfig_t cfg = {};
        cfg.gridDim  = dim3(B_ * NY_, 1, 1);
        cfg.blockDim = dim3(TPB, 1, 1);
        cfg.attrs    = attr;
        cfg.numAttrs = 1;
        cudaLaunchKernelEx(&cfg, gather_tma_kernel, feat, tmap);
    } else {
        gather_fallback_kernel<<<B_ * NY_ * TILES_X, TPB>>>(feat, (float*)d_out);
    }
}

// round 16
// speedup vs baseline: 1.0962x; 1.0026x over previous
#include <cuda_runtime.h>
#include <cuda.h>
#include <cstdint>

// PointPillarScatter on GB300 (sm_103a).
// out[b, c, y, x] = feat[p, c] where idxmap cell == p+1, else 0.
//
// Round 15 -> 16: chunk-count series said fewer/larger chunks win
// (16 chunks regressed vs 8). Extrapolate once: 4 chunks of 16 channels.
// Buffers 2 x 27.6 KB -> dynamic smem (55.3 KB, attribute-raised).
// Half the barriers, same bytes, more TMA bytes in flight per SM.
// Everything else = the proven R12 structure (PDL scatter overlap,
// self-cleaning idxmap, STG fallback).

#define NX_ 432
#define NY_ 496
#define C_  64
#define B_  8
#define NCELLS (B_ * NY_ * NX_)      // 1,714,176
#define CHUNK_C 16                   // channels per TMA store
#define NCHUNKS (C_ / CHUNK_C)       // 4
#define SBUF_BYTES (2 * CHUNK_C * NX_ * 4)   // 55,296

__device__ __align__(16) int g_idxmap[NCELLS];   // zero-init = all empty

// ---------------------------------------------------------------------------
// Kernel 1: scatter pillar index (p+1), with per-block dtype detection.
// ---------------------------------------------------------------------------
__global__ void scatter_idx_kernel(const void* __restrict__ coords, int P) {
    __shared__ int s_is64;
    if (threadIdx.x < 32) {
        const long long* c64 = (const long long*)coords;
        int rows = P < 64 ? P : 64;
        int ok = 1;
        for (int p = threadIdx.x; p < rows; p += 32) {
            for (int j = 0; j < 4; j++) {
                long long v = c64[4 * p + j];
                if (v < 0 || v >= (1LL << 20)) ok = 0;
            }
        }
        ok = __all_sync(0xFFFFFFFFu, ok);
        if (threadIdx.x == 0) s_is64 = ok;
    }
    __syncthreads();

    int p = blockIdx.x * blockDim.x + threadIdx.x;
    if (p < P) {
        int b, z, y, x;
        if (s_is64) {
            const long long* c = (const long long*)coords;
            b = (int)c[4 * p + 0]; z = (int)c[4 * p + 1];
            y = (int)c[4 * p + 2]; x = (int)c[4 * p + 3];
        } else {
            const int* c = (const int*)coords;
            b = c[4 * p + 0]; z = c[4 * p + 1];
            y = c[4 * p + 2]; x = c[4 * p + 3];
        }
        if (b >= 0 && b < B_) {
            int lin = z + y * NX_ + x;
            if (lin >= 0 && lin < NY_ * NX_)
                g_idxmap[b * (NY_ * NX_) + lin] = p + 1;  // 0 stays "empty"
        }
    }
    cudaTriggerProgrammaticLaunchCompletion();
}

// ---------------------------------------------------------------------------
__device__ __forceinline__ uint32_t smem_u32(const void* p) {
    uint32_t a;
    asm("{ .reg .u64 t; cvta.to.shared.u64 t, %1; cvt.u32.u64 %0, t; }"
        : "=r"(a) : "l"(p));
    return a;
}

// ---------------------------------------------------------------------------
// Kernel 2 (TMA path): block = one (b, y) row of 432 cells.
// 4 chunks of 16 channels; two 27.6 KB dynamic-smem buffers.
// ---------------------------------------------------------------------------
__global__ __launch_bounds__(256) void gather_tma_kernel(
    const float* __restrict__ feat,
    const __grid_constant__ CUtensorMap tmap)
{
    extern __shared__ __align__(128) float s_dyn[];  // [2][CHUNK_C][NX_]
    __shared__ int s_list[NX_];      // (p << 9) | cell
    __shared__ int s_n;

    int tid = threadIdx.x;
    int y = blockIdx.x % NY_;
    int b = blockIdx.x / NY_;

    if (tid == 0) s_n = 0;
    // Zero both buffers ONCE (scatter-independent; overlaps scatter via PDL).
    // Zeros persist: buffer reuse overwrites exactly the same occupied cells.
    float4* z = (float4*)s_dyn;
    #pragma unroll 4
    for (int i = tid; i < 2 * CHUNK_C * NX_ / 4; i += 256)
        z[i] = make_float4(0.0f, 0.0f, 0.0f, 0.0f);

    // Wait for the scatter grid's writes to be visible.
    cudaGridDependencySynchronize();
    __syncthreads();

    // Phase 1: idxmap read + self-clean + compact occupied cells.
    int cellbase = b * (NY_ * NX_) + y * NX_;
    for (int cell = tid; cell < NX_; cell += 256) {
        int m = g_idxmap[cellbase + cell];
        if (m != 0) {
            g_idxmap[cellbase + cell] = 0;       // restore for next replay
            int pos = atomicAdd(&s_n, 1);
            s_list[pos] = ((m - 1) << 9) | cell; // p, cell packed
        }
    }
    __syncthreads();
    int n_occ = s_n;
    const float4* feat4 = (const float4*)feat;

    for (int chunk = 0; chunk < NCHUNKS; chunk++) {
        float* buf = s_dyn + (chunk & 1) * (CHUNK_C * NX_);
        // Fill occupied cells: 4 float4 (64B) per pillar for this chunk.
        for (int j = tid; j < n_occ * 4; j += 256) {
            int slot = j >> 2;
            int v    = j & 3;
            int e    = s_list[slot];
            int cell = e & 511;
            int p    = e >> 9;
            float4 f = feat4[(size_t)p * 16 + chunk * 4 + v];
            buf[(4 * v + 0) * NX_ + cell] = f.x;
            buf[(4 * v + 1) * NX_ + cell] = f.y;
            buf[(4 * v + 2) * NX_ + cell] = f.z;
            buf[(4 * v + 3) * NX_ + cell] = f.w;
        }
        __syncthreads();
        if (tid == 0) {
            asm volatile("fence.proxy.async.shared::cta;" ::: "memory");
            uint32_t saddr = smem_u32(buf);
            int c0 = chunk * CHUNK_C;
            asm volatile(
                "cp.async.bulk.tensor.5d.global.shared::cta.tile.bulk_group "
                "[%0, {%1, %2, %3, %4, %5}], [%6];"
                :: "l"(&tmap), "r"(0), "r"(0), "r"(c0), "r"(y), "r"(b),
                   "r"(saddr)
                : "memory");
            asm volatile("cp.async.bulk.commit_group;" ::: "memory");
            // <=1 group pending -> chunk-1 done -> other buffer free.
            asm volatile("cp.async.bulk.wait_group 1;" ::: "memory");
        }
        __syncthreads();
    }
    if (tid == 0) asm volatile("cp.async.bulk.wait_group 0;" ::: "memory");
}

// ---------------------------------------------------------------------------
// Fallback gather (proven R10 path), used only if driver entry lookup fails.
// ---------------------------------------------------------------------------
#define TILE   108
#define TILES_X (NX_ / TILE)
#define QUADS  (TILE / 4)
#define CGROUPS 10
#define SLOTS  (QUADS * CGROUPS)
#define PITCH  116
#define CH_    32

__global__ __launch_bounds__(256) void gather_fallback_kernel(
    const float* __restrict__ feat, float* __restrict__ out)
{
    __shared__ float s_tile[CH_][PITCH];
    __shared__ __align__(16) int s_idx[PITCH];
    __shared__ int s_list[TILE];
    __shared__ int s_n;

    int bx = blockIdx.x;
    int tx = bx % TILES_X;
    int y  = (bx / TILES_X) % NY_;
    int b  = bx / (TILES_X * NY_);
    int x0 = tx * TILE;
    int tid = threadIdx.x;

    if (tid == 0) s_n = 0;
    if (tid >= TILE && tid < PITCH) s_idx[tid] = -1;
    __syncthreads();

    int cellbase = b * (NY_ * NX_) + y * NX_ + x0;
    if (tid < TILE) {
        int m = g_idxmap[cellbase + tid];
        if (m != 0) g_idxmap[cellbase + tid] = 0;
        s_idx[tid] = m - 1;
        if (m > 0) { int pos = atomicAdd(&s_n, 1); s_list[pos] = tid; }
    }
    __syncthreads();

    int n_occ = s_n;
    const float4* feat4 = (const float4*)feat;
    size_t outbase = (size_t)b * (C_ * NY_ * NX_) + (size_t)y * NX_ + x0;
    const int4* s_idx4 = (const int4*)s_idx;

    #pragma unroll
    for (int half = 0; half < 2; half++) {
        for (int j = tid; j < n_occ * 8; j += 256) {
            int slot = j >> 3, v = j & 7;
            int cell = s_list[slot];
            int p    = s_idx[cell];
            float4 f = feat4[(size_t)p * 16 + half * 8 + v];
            s_tile[4 * v + 0][cell] = f.x;
            s_tile[4 * v + 1][cell] = f.y;
            s_tile[4 * v + 2][cell] = f.z;
            s_tile[4 * v + 3][cell] = f.w;
        }
        __syncthreads();
        const float* outh = out + outbase + (size_t)(half * CH_) * (NY_ * NX_);
        for (int slot = tid; slot < SLOTS; slot += 256) {
            int q = slot % QUADS, c0 = slot / QUADS;
            int4 m = s_idx4[q];
            bool any = (m.x >= 0) | (m.y >= 0) | (m.z >= 0) | (m.w >= 0);
            const float* outq = outh + 4 * q;
            #pragma unroll
            for (int c = 0; c < CH_; c += CGROUPS) {
                int cc = c + c0;
                if (cc >= CH_) break;
                float4 v = make_float4(0.0f, 0.0f, 0.0f, 0.0f);
                if (any) {
                    float4 t = ((const float4*)s_tile[cc])[q];
                    if (m.x >= 0) v.x = t.x;
                    if (m.y >= 0) v.y = t.y;
                    if (m.z >= 0) v.z = t.z;
                    if (m.w >= 0) v.w = t.w;
                }
                __stcs((float4*)(outq + (size_t)cc * (NY_ * NX_)), v);
            }
        }
        if (half == 0) __syncthreads();
    }
}

// ---------------------------------------------------------------------------
typedef CUresult (*EncodeFn)(CUtensorMap*, CUtensorMapDataType, cuuint32_t,
    void*, const cuuint64_t*, const cuuint64_t*, const cuuint32_t*,
    const cuuint32_t*, CUtensorMapInterleave, CUtensorMapSwizzle,
    CUtensorMapL2promotion, CUtensorMapFloatOOBfill);

extern "C" void kernel_launch(void* const* d_in, const int* in_sizes, int n_in,
                              void* d_out, int out_size) {
    const float* feat   = (const float*)d_in[0];
    const void*  coords = d_in[1];
    int P = in_sizes[0] / C_;   // features are [P, 64] f32

    constexpr int TPB = 256;
    scatter_idx_kernel<<<(P + TPB - 1) / TPB, TPB>>>(coords, P);

    // Build the 5D output tensor map: [x_in=216, x_out=2, c, y, b].
    EncodeFn enc = nullptr;
    cudaDriverEntryPointQueryResult qr = cudaDriverEntryPointSymbolNotFound;
    cudaGetDriverEntryPointByVersion("cuTensorMapEncodeTiled", (void**)&enc,
                                     12000, cudaEnableDefault, &qr);
    bool tma_ok = (enc != nullptr) && (qr == cudaDriverEntryPointSuccess);

    CUtensorMap tmap;
    if (tma_ok) {
        cuuint64_t dims[5]    = {216, 2, C_, NY_, B_};
        cuuint64_t strides[4] = {216ull * 4,                       // x_out
                                 (cuuint64_t)NY_ * NX_ * 4,        // c
                                 (cuuint64_t)NX_ * 4,              // y
                                 (cuuint64_t)C_ * NY_ * NX_ * 4};  // b
        cuuint32_t box[5]  = {216, 2, CHUNK_C, 1, 1};
        cuuint32_t estr[5] = {1, 1, 1, 1, 1};
        CUresult r = enc(&tmap, CU_TENSOR_MAP_DATA_TYPE_FLOAT32, 5, d_out,
                         dims, strides, box, estr,
                         CU_TENSOR_MAP_INTERLEAVE_NONE,
                         CU_TENSOR_MAP_SWIZZLE_NONE,
                         CU_TENSOR_MAP_L2_PROMOTION_L2_128B,
                         CU_TENSOR_MAP_FLOAT_OOB_FILL_NONE);
        if (r != CUDA_SUCCESS) tma_ok = false;
    }

    if (tma_ok) {
        // Raise the dynamic smem cap for the 55.3 KB double buffer.
        if (cudaFuncSetAttribute(gather_tma_kernel,
                                 cudaFuncAttributeMaxDynamicSharedMemorySize,
                                 SBUF_BYTES) != cudaSuccess) {
            tma_ok = false;
        }
    }

    if (tma_ok) {
        cudaLaunchAttribute attr[1];
        attr[0].id = cudaLaunchAttributeProgrammaticStreamSerialization;
        attr[0].val.programmaticStreamSerializationAllowed = 1;
        cudaLaunchConfig_t cfg = {};
        cfg.gridDim  = dim3(B_ * NY_, 1, 1);
        cfg.blockDim = dim3(TPB, 1, 1);
        cfg.dynamicSmemBytes = SBUF_BYTES;
        cfg.attrs    = attr;
        cfg.numAttrs = 1;
        cudaLaunchKernelEx(&cfg, gather_tma_kernel, feat, tmap);
    } else {
        gather_fallback_kernel<<<B_ * NY_ * TILES_X, TPB>>>(feat, (float*)d_out);
    }
}

// round 17
// speedup vs baseline: 1.1106x; 1.0132x over previous
#include <cuda_runtime.h>
#include <cuda.h>
#include <cstdint>

// PointPillarScatter on GB300 (sm_103a) — FINAL.
// out[b, c, y, x] = feat[p, c] where idxmap cell == p+1, else 0.
//
// Converged configuration (best measured: 84.4 us, R12):
//  - Kernel 1: scatter pillar INDEX (p+1; 0 = empty) into a zero-init
//    __device__ idxmap, with on-device coords-dtype detection (the dataset
//    materializes the reference's int64 coords as int32).
//  - Kernel 2: per-(b,y)-row gather; two 13.8 KB smem buffers zeroed once
//    (occupied-cell set is identical across channel chunks, so chunk fills
//    overwrite exactly the stale cells); 8 chunks of 8 channels streamed
//    out via cp.async.bulk.tensor (TMA) double-buffered with
//    commit_group/wait_group 1. Self-cleans idxmap for graph-replay
//    determinism. PDL overlaps the scatter with the zeroing prologue.
//  - Fallback STG gather if the cuTensorMapEncodeTiled entry is missing.
//
// Measured roofline: gather 78.1 us @ 5.4 TB/s (68% DRAM). Four TMA shapes
// (depth 2/4, 4/8/16-channel chunks, occ 44-89%) all land within noise ->
// the memory system, not the kernel, sets this floor.

#define NX_ 432
#define NY_ 496
#define C_  64
#define B_  8
#define NCELLS (B_ * NY_ * NX_)      // 1,714,176
#define CHUNK_C 8                    // channels per TMA store
#define NCHUNKS (C_ / CHUNK_C)       // 8

__device__ __align__(16) int g_idxmap[NCELLS];   // zero-init = all empty

// ---------------------------------------------------------------------------
// Kernel 1: scatter pillar index (p+1), with per-block dtype detection.
// ---------------------------------------------------------------------------
__global__ void scatter_idx_kernel(const void* __restrict__ coords, int P) {
    __shared__ int s_is64;
    if (threadIdx.x < 32) {
        const long long* c64 = (const long long*)coords;
        int rows = P < 64 ? P : 64;
        int ok = 1;
        for (int p = threadIdx.x; p < rows; p += 32) {
            for (int j = 0; j < 4; j++) {
                long long v = c64[4 * p + j];
                if (v < 0 || v >= (1LL << 20)) ok = 0;
            }
        }
        ok = __all_sync(0xFFFFFFFFu, ok);
        if (threadIdx.x == 0) s_is64 = ok;
    }
    __syncthreads();

    int p = blockIdx.x * blockDim.x + threadIdx.x;
    if (p < P) {
        int b, z, y, x;
        if (s_is64) {
            const long long* c = (const long long*)coords;
            b = (int)c[4 * p + 0]; z = (int)c[4 * p + 1];
            y = (int)c[4 * p + 2]; x = (int)c[4 * p + 3];
        } else {
            const int* c = (const int*)coords;
            b = c[4 * p + 0]; z = c[4 * p + 1];
            y = c[4 * p + 2]; x = c[4 * p + 3];
        }
        if (b >= 0 && b < B_) {
            int lin = z + y * NX_ + x;
            if (lin >= 0 && lin < NY_ * NX_)
                g_idxmap[b * (NY_ * NX_) + lin] = p + 1;  // 0 stays "empty"
        }
    }
    // Let the dependent gather grid begin launching (it still gridsyncs on
    // our full completion before reading idxmap).
    cudaTriggerProgrammaticLaunchCompletion();
}

// ---------------------------------------------------------------------------
__device__ __forceinline__ uint32_t smem_u32(const void* p) {
    uint32_t a;
    asm("{ .reg .u64 t; cvta.to.shared.u64 t, %1; cvt.u32.u64 %0, t; }"
        : "=r"(a) : "l"(p));
    return a;
}

// ---------------------------------------------------------------------------
// Kernel 2 (TMA path): block = one (b, y) row of 432 cells.
// ---------------------------------------------------------------------------
__global__ __launch_bounds__(256) void gather_tma_kernel(
    const float* __restrict__ feat,
    const __grid_constant__ CUtensorMap tmap)
{
    __shared__ __align__(128) float s_buf[2][CHUNK_C][NX_];  // 2 x 13,824 B
    __shared__ int s_list[NX_];      // (p << 9) | cell
    __shared__ int s_n;

    int tid = threadIdx.x;
    int y = blockIdx.x % NY_;
    int b = blockIdx.x / NY_;

    if (tid == 0) s_n = 0;
    // Zero both buffers ONCE (scatter-independent; overlaps with scatter
    // under PDL). Zeros persist; chunk fills overwrite the same cells.
    float4* z = (float4*)&s_buf[0][0][0];
    #pragma unroll 4
    for (int i = tid; i < 2 * CHUNK_C * NX_ / 4; i += 256)
        z[i] = make_float4(0.0f, 0.0f, 0.0f, 0.0f);

    // Wait for the scatter grid's writes to be visible.
    cudaGridDependencySynchronize();
    __syncthreads();

    // Phase 1: idxmap read + self-clean + compact occupied cells.
    int cellbase = b * (NY_ * NX_) + y * NX_;
    for (int cell = tid; cell < NX_; cell += 256) {
        int m = g_idxmap[cellbase + cell];
        if (m != 0) {
            g_idxmap[cellbase + cell] = 0;       // restore for next replay
            int pos = atomicAdd(&s_n, 1);
            s_list[pos] = ((m - 1) << 9) | cell; // p, cell packed
        }
    }
    __syncthreads();
    int n_occ = s_n;
    const float4* feat4 = (const float4*)feat;

    for (int chunk = 0; chunk < NCHUNKS; chunk++) {
        float (*buf)[NX_] = s_buf[chunk & 1];
        // Fill occupied cells: 2 float4 (32B) per pillar for this chunk.
        for (int j = tid; j < n_occ * 2; j += 256) {
            int slot = j >> 1;
            int v    = j & 1;
            int e    = s_list[slot];
            int cell = e & 511;
            int p    = e >> 9;
            float4 f = feat4[(size_t)p * 16 + chunk * 2 + v];
            buf[4 * v + 0][cell] = f.x;
            buf[4 * v + 1][cell] = f.y;
            buf[4 * v + 2][cell] = f.z;
            buf[4 * v + 3][cell] = f.w;
        }
        __syncthreads();
        if (tid == 0) {
            asm volatile("fence.proxy.async.shared::cta;" ::: "memory");
            uint32_t saddr = smem_u32(&buf[0][0]);
            int c0 = chunk * CHUNK_C;
            asm volatile(
                "cp.async.bulk.tensor.5d.global.shared::cta.tile.bulk_group "
                "[%0, {%1, %2, %3, %4, %5}], [%6];"
                :: "l"(&tmap), "r"(0), "r"(0), "r"(c0), "r"(y), "r"(b),
                   "r"(saddr)
                : "memory");
            asm volatile("cp.async.bulk.commit_group;" ::: "memory");
            // <=1 group pending -> chunk-1 done -> other buffer free.
            asm volatile("cp.async.bulk.wait_group 1;" ::: "memory");
        }
        __syncthreads();
    }
    if (tid == 0) asm volatile("cp.async.bulk.wait_group 0;" ::: "memory");
}

// ---------------------------------------------------------------------------
// Fallback gather (proven R10 path), used only if driver entry lookup fails.
// ---------------------------------------------------------------------------
#define TILE   108
#define TILES_X (NX_ / TILE)
#define QUADS  (TILE / 4)
#define CGROUPS 10
#define SLOTS  (QUADS * CGROUPS)
#define PITCH  116
#define CH_    32

__global__ __launch_bounds__(256) void gather_fallback_kernel(
    const float* __restrict__ feat, float* __restrict__ out)
{
    __shared__ float s_tile[CH_][PITCH];
    __shared__ __align__(16) int s_idx[PITCH];
    __shared__ int s_list[TILE];
    __shared__ int s_n;

    int bx = blockIdx.x;
    int tx = bx % TILES_X;
    int y  = (bx / TILES_X) % NY_;
    int b  = bx / (TILES_X * NY_);
    int x0 = tx * TILE;
    int tid = threadIdx.x;

    if (tid == 0) s_n = 0;
    if (tid >= TILE && tid < PITCH) s_idx[tid] = -1;
    __syncthreads();

    int cellbase = b * (NY_ * NX_) + y * NX_ + x0;
    if (tid < TILE) {
        int m = g_idxmap[cellbase + tid];
        if (m != 0) g_idxmap[cellbase + tid] = 0;
        s_idx[tid] = m - 1;
        if (m > 0) { int pos = atomicAdd(&s_n, 1); s_list[pos] = tid; }
    }
    __syncthreads();

    int n_occ = s_n;
    const float4* feat4 = (const float4*)feat;
    size_t outbase = (size_t)b * (C_ * NY_ * NX_) + (size_t)y * NX_ + x0;
    const int4* s_idx4 = (const int4*)s_idx;

    #pragma unroll
    for (int half = 0; half < 2; half++) {
        for (int j = tid; j < n_occ * 8; j += 256) {
            int slot = j >> 3, v = j & 7;
            int cell = s_list[slot];
            int p    = s_idx[cell];
            float4 f = feat4[(size_t)p * 16 + half * 8 + v];
            s_tile[4 * v + 0][cell] = f.x;
            s_tile[4 * v + 1][cell] = f.y;
            s_tile[4 * v + 2][cell] = f.z;
            s_tile[4 * v + 3][cell] = f.w;
        }
        __syncthreads();
        const float* outh = out + outbase + (size_t)(half * CH_) * (NY_ * NX_);
        for (int slot = tid; slot < SLOTS; slot += 256) {
            int q = slot % QUADS, c0 = slot / QUADS;
            int4 m = s_idx4[q];
            bool any = (m.x >= 0) | (m.y >= 0) | (m.z >= 0) | (m.w >= 0);
            const float* outq = outh + 4 * q;
            #pragma unroll
            for (int c = 0; c < CH_; c += CGROUPS) {
                int cc = c + c0;
                if (cc >= CH_) break;
                float4 v = make_float4(0.0f, 0.0f, 0.0f, 0.0f);
                if (any) {
                    float4 t = ((const float4*)s_tile[cc])[q];
                    if (m.x >= 0) v.x = t.x;
                    if (m.y >= 0) v.y = t.y;
                    if (m.z >= 0) v.z = t.z;
                    if (m.w >= 0) v.w = t.w;
                }
                __stcs((float4*)(outq + (size_t)cc * (NY_ * NX_)), v);
            }
        }
        if (half == 0) __syncthreads();
    }
}

// ---------------------------------------------------------------------------
typedef CUresult (*EncodeFn)(CUtensorMap*, CUtensorMapDataType, cuuint32_t,
    void*, const cuuint64_t*, const cuuint64_t*, const cuuint32_t*,
    const cuuint32_t*, CUtensorMapInterleave, CUtensorMapSwizzle,
    CUtensorMapL2promotion, CUtensorMapFloatOOBfill);

extern "C" void kernel_launch(void* const* d_in, const int* in_sizes, int n_in,
                              void* d_out, int out_size) {
    const float* feat   = (const float*)d_in[0];
    const void*  coords = d_in[1];
    int P = in_sizes[0] / C_;   // features are [P, 64] f32

    constexpr int TPB = 256;
    scatter_idx_kernel<<<(P + TPB - 1) / TPB, TPB>>>(coords, P);

    // Build the 5D output tensor map: [x_in=216, x_out=2, c, y, b].
    EncodeFn enc = nullptr;
    cudaDriverEntryPointQueryResult qr = cudaDriverEntryPointSymbolNotFound;
    cudaGetDriverEntryPointByVersion("cuTensorMapEncodeTiled", (void**)&enc,
                                     12000, cudaEnableDefault, &qr);
    bool tma_ok = (enc != nullptr) && (qr == cudaDriverEntryPointSuccess);

    CUtensorMap tmap;
    if (tma_ok) {
        cuuint64_t dims[5]    = {216, 2, C_, NY_, B_};
        cuuint64_t strides[4] = {216ull * 4,                       // x_out
                                 (cuuint64_t)NY_ * NX_ * 4,        // c
                                 (cuuint64_t)NX_ * 4,              // y
                                 (cuuint64_t)C_ * NY_ * NX_ * 4};  // b
        cuuint32_t box[5]  = {216, 2, CHUNK_C, 1, 1};
        cuuint32_t estr[5] = {1, 1, 1, 1, 1};
        CUresult r = enc(&tmap, CU_TENSOR_MAP_DATA_TYPE_FLOAT32, 5, d_out,
                         dims, strides, box, estr,
                         CU_TENSOR_MAP_INTERLEAVE_NONE,
                         CU_TENSOR_MAP_SWIZZLE_NONE,
                         CU_TENSOR_MAP_L2_PROMOTION_L2_128B,
                         CU_TENSOR_MAP_FLOAT_OOB_FILL_NONE);
        if (r != CUDA_SUCCESS) tma_ok = false;
    }

    if (tma_ok) {
        // PDL launch: overlap gather's zeroing prologue with the scatter.
        cudaLaunchAttribute attr[1];
        attr[0].id = cudaLaunchAttributeProgrammaticStreamSerialization;
        attr[0].val.programmaticStreamSerializationAllowed = 1;
        cudaLaunchConfig_t cfg = {};
        cfg.gridDim  = dim3(B_ * NY_, 1, 1);
        cfg.blockDim = dim3(TPB, 1, 1);
        cfg.attrs    = attr;
        cfg.numAttrs = 1;
        cudaLaunchKernelEx(&cfg, gather_tma_kernel, feat, tmap);
    } else {
        gather_fallback_kernel<<<B_ * NY_ * TILES_X, TPB>>>(feat, (float*)d_out);
    }
}